// round 3
// baseline (speedup 1.0000x reference)
#include <cuda_runtime.h>
#include <cstdint>
#include <cstddef>

// ---------------------------------------------------------------------------
// JointSampling: gumbel-softmax (disc) + reparameterized gaussian (cont)
// Reproduces JAX threefry2x32 PARTITIONABLE bit streams:
//   random_bits32(key, i) = x0 ^ x1 of threefry(key, (hi(i)=0, lo(i)=i))
//   split(key)[i]         = both output words of threefry(key, (0, i))
// Input : latent [B, 3072] f32  (2048 disc alphas as 32x64, then 512 (mean,logvar) pairs)
// Output: [ sample (B*2560) | mean (B*512) | logvar (B*512) ]  f32
// ---------------------------------------------------------------------------

#define N_CATEG 32
#define CATEG_N 64
#define DISC_LEN 2048
#define CONT_LEN 512
#define ROW_LEN 3072
#define SAMPLE_LEN 2560

static __host__ __device__ __forceinline__ uint32_t rotl32(uint32_t x, int r) {
#ifdef __CUDA_ARCH__
    return __funnelshift_l(x, x, r);
#else
    return (x << r) | (x >> (32 - r));
#endif
}

// JAX threefry2x32 block. In/out in x0, x1.
static __host__ __device__ __forceinline__ void threefry2x32(
    uint32_t k0, uint32_t k1, uint32_t& x0, uint32_t& x1) {
    uint32_t ks2 = k0 ^ k1 ^ 0x1BD11BDAu;
    x0 += k0; x1 += k1;
#define TF_R(r) { x0 += x1; x1 = rotl32(x1, r); x1 ^= x0; }
    TF_R(13) TF_R(15) TF_R(26) TF_R(6)
    x0 += k1;  x1 += ks2 + 1u;
    TF_R(17) TF_R(29) TF_R(16) TF_R(24)
    x0 += ks2; x1 += k0 + 2u;
    TF_R(13) TF_R(15) TF_R(26) TF_R(6)
    x0 += k0;  x1 += k1 + 3u;
    TF_R(17) TF_R(29) TF_R(16) TF_R(24)
    x0 += k1;  x1 += ks2 + 4u;
    TF_R(13) TF_R(15) TF_R(26) TF_R(6)
    x0 += ks2; x1 += k0 + 5u;
#undef TF_R
}

// Partitionable random_bits(32): counter (0, i); output = XOR of both words.
static __device__ __forceinline__ uint32_t tf_bits32(uint32_t k0, uint32_t k1, uint32_t idx) {
    uint32_t x0 = 0u, x1 = idx;
    threefry2x32(k0, k1, x0, x1);
    return x0 ^ x1;
}

static __device__ __forceinline__ float bits_to_u01(uint32_t bits) {
    // bitcast((bits>>9) | 0x3f800000) - 1  in [0,1)
    return __uint_as_float((bits >> 9) | 0x3F800000u) - 1.0f;
}

// XLA f32 erfinv (Giles polynomial)
static __device__ __forceinline__ float erfinv_f32(float x) {
    float w = -log1pf(-x * x);
    float p;
    if (w < 5.0f) {
        w -= 2.5f;
        p = 2.81022636e-08f;
        p = fmaf(p, w, 3.43273939e-07f);
        p = fmaf(p, w, -3.5233877e-06f);
        p = fmaf(p, w, -4.39150654e-06f);
        p = fmaf(p, w, 0.00021858087f);
        p = fmaf(p, w, -0.00125372503f);
        p = fmaf(p, w, -0.00417768164f);
        p = fmaf(p, w, 0.246640727f);
        p = fmaf(p, w, 1.50140941f);
    } else {
        w = sqrtf(w) - 3.0f;
        p = -0.000200214257f;
        p = fmaf(p, w, 0.000100950558f);
        p = fmaf(p, w, 0.00134934322f);
        p = fmaf(p, w, -0.00367342844f);
        p = fmaf(p, w, 0.00573950773f);
        p = fmaf(p, w, -0.0076224613f);
        p = fmaf(p, w, 0.00943887047f);
        p = fmaf(p, w, 1.00167406f);
        p = fmaf(p, w, 2.83297682f);
    }
    return p * x;
}

// ---------------------------------------------------------------------------
// Disc branch: one warp per (b, categ) group of 64 logits; 2 elems/thread.
// ---------------------------------------------------------------------------
__global__ void __launch_bounds__(256)
disc_kernel(const float* __restrict__ latent, float* __restrict__ out,
            uint32_t kg0, uint32_t kg1, int n_groups) {
    int warp_global = (blockIdx.x * blockDim.x + threadIdx.x) >> 5;
    if (warp_global >= n_groups) return;
    int lane = threadIdx.x & 31;

    int b = warp_global >> 5;          // / N_CATEG
    int g = warp_global & 31;          // % N_CATEG

    const float* row = latent + (size_t)b * ROW_LEN + (size_t)g * CATEG_N;
    float a0 = row[lane];
    float a1 = row[lane + 32];

    // softmax #1 over the 64 logits
    float m = fmaxf(a0, a1);
#pragma unroll
    for (int o = 16; o; o >>= 1) m = fmaxf(m, __shfl_xor_sync(0xffffffffu, m, o));
    float e0 = __expf(a0 - m);
    float e1 = __expf(a1 - m);
    float s = e0 + e1;
#pragma unroll
    for (int o = 16; o; o >>= 1) s += __shfl_xor_sync(0xffffffffu, s, o);
    float rinv = 1.0f / s;
    float p0 = e0 * rinv;
    float p1 = e1 * rinv;

    // gumbel noise: uniform over flat (B, 32, 64) index, key kg
    uint32_t base = ((uint32_t)warp_global << 6) + (uint32_t)lane;
    uint32_t bits0 = tf_bits32(kg0, kg1, base);
    uint32_t bits1 = tf_bits32(kg0, kg1, base + 32u);
    const float TINY = 1.17549435e-38f;
    float u0 = fmaxf(TINY, bits_to_u01(bits0));
    float u1 = fmaxf(TINY, bits_to_u01(bits1));
    float g0 = -__logf(-__logf(u0));
    float g1 = -__logf(-__logf(u1));

    // softmax #2 over (probs + gumbel)/tau, tau = 0.5
    float t0 = (p0 + g0) * 2.0f;
    float t1 = (p1 + g1) * 2.0f;
    float m2 = fmaxf(t0, t1);
#pragma unroll
    for (int o = 16; o; o >>= 1) m2 = fmaxf(m2, __shfl_xor_sync(0xffffffffu, m2, o));
    float f0 = __expf(t0 - m2);
    float f1 = __expf(t1 - m2);
    float s2 = f0 + f1;
#pragma unroll
    for (int o = 16; o; o >>= 1) s2 += __shfl_xor_sync(0xffffffffu, s2, o);
    float r2 = 1.0f / s2;

    float* orow = out + (size_t)b * SAMPLE_LEN + (size_t)g * CATEG_N;
    orow[lane]      = f0 * r2;
    orow[lane + 32] = f1 * r2;
}

// ---------------------------------------------------------------------------
// Cont branch: elementwise over B*512; writes cont part of sample + mean + logvar.
// ---------------------------------------------------------------------------
__global__ void __launch_bounds__(256)
cont_kernel(const float* __restrict__ latent, float* __restrict__ out,
            uint32_t kn0, uint32_t kn1, int n_elems, int B) {
    int i = blockIdx.x * blockDim.x + threadIdx.x;
    if (i >= n_elems) return;
    int b = i >> 9;        // / CONT_LEN
    int j = i & 511;       // % CONT_LEN

    const float2* cptr = (const float2*)(latent + (size_t)b * ROW_LEN + DISC_LEN);
    float2 ml = cptr[j];
    float mean = ml.x, logvar = ml.y;

    // normal(kn): u in [nextafter(-1,0), 1); eps = sqrt(2)*erfinv(u)
    uint32_t bits = tf_bits32(kn0, kn1, (uint32_t)i);
    float u01 = bits_to_u01(bits);
    const float LO = -0.99999994f;      // nextafter(-1, 0) in f32
    float u = fmaxf(LO, fmaf(u01, 2.0f, LO));   // (hi-lo) rounds to exactly 2.0f
    float eps = 1.41421356f * erfinv_f32(u);

    float cs = fmaf(__expf(0.5f * logvar), eps, mean);

    size_t sample_total = (size_t)B * SAMPLE_LEN;
    out[(size_t)b * SAMPLE_LEN + DISC_LEN + j] = cs;
    out[sample_total + (size_t)i] = mean;
    out[sample_total + (size_t)B * CONT_LEN + (size_t)i] = logvar;
}

// ---------------------------------------------------------------------------
// Launch
// ---------------------------------------------------------------------------
extern "C" void kernel_launch(void* const* d_in, const int* in_sizes, int n_in,
                              void* d_out, int out_size) {
    const float* latent = (const float*)d_in[0];
    float* out = (float*)d_out;
    int B = in_sizes[0] / ROW_LEN;

    // Partitionable split of key(42) = (0, 42):
    //   subkey[i] = both output words of threefry2x32((0,42), (0, i))
    uint32_t kg0 = 0u, kg1 = 0u;       // counter (0,0)
    threefry2x32(0u, 42u, kg0, kg1);
    uint32_t kn0 = 0u, kn1 = 1u;       // counter (0,1)
    threefry2x32(0u, 42u, kn0, kn1);

    int n_groups = B * N_CATEG;                       // warps for disc
    int disc_threads = 256;
    int disc_blocks = (n_groups * 32 + disc_threads - 1) / disc_threads;
    disc_kernel<<<disc_blocks, disc_threads>>>(latent, out, kg0, kg1, n_groups);

    int n_cont = B * CONT_LEN;
    int cont_threads = 256;
    int cont_blocks = (n_cont + cont_threads - 1) / cont_threads;
    cont_kernel<<<cont_blocks, cont_threads>>>(latent, out, kn0, kn1, n_cont, B);
}

// round 4
// speedup vs baseline: 1.1171x; 1.1171x over previous
#include <cuda_runtime.h>
#include <cstdint>
#include <cstddef>

// ---------------------------------------------------------------------------
// JointSampling: gumbel-softmax (disc) + reparameterized gaussian (cont)
// JAX partitionable threefry2x32:
//   random_bits32(key, i) = x0 ^ x1 of threefry(key, (0, i))
//   split(key)[i]         = both output words of threefry(key, (0, i))
// Input : latent [B, 3072] f32
// Output: [ sample (B*2560) | mean (B*512) | logvar (B*512) ]  f32
// ---------------------------------------------------------------------------

#define N_CATEG 32
#define CATEG_N 64
#define DISC_LEN 2048
#define CONT_LEN 512
#define ROW_LEN 3072
#define SAMPLE_LEN 2560

static __host__ __device__ __forceinline__ uint32_t rotl32(uint32_t x, int r) {
#ifdef __CUDA_ARCH__
    return __funnelshift_l(x, x, r);
#else
    return (x << r) | (x >> (32 - r));
#endif
}

// opaque-multiplier add: emits IMAD.LO (fma pipe) because `one` is a runtime reg
static __device__ __forceinline__ uint32_t madd(uint32_t a, uint32_t one, uint32_t c) {
    return a * one + c;
}

// Host-side reference threefry (plain adds)
static __host__ void threefry2x32_host(uint32_t k0, uint32_t k1, uint32_t& x0, uint32_t& x1) {
    uint32_t ks2 = k0 ^ k1 ^ 0x1BD11BDAu;
    x0 += k0; x1 += k1;
#define TFH(r) { x0 += x1; x1 = (x1 << r) | (x1 >> (32 - r)); x1 ^= x0; }
    TFH(13) TFH(15) TFH(26) TFH(6)
    x0 += k1;  x1 += ks2 + 1u;
    TFH(17) TFH(29) TFH(16) TFH(24)
    x0 += ks2; x1 += k0 + 2u;
    TFH(13) TFH(15) TFH(26) TFH(6)
    x0 += k0;  x1 += k1 + 3u;
    TFH(17) TFH(29) TFH(16) TFH(24)
    x0 += k1;  x1 += ks2 + 4u;
    TFH(13) TFH(15) TFH(26) TFH(6)
    x0 += ks2; x1 += k0 + 5u;
#undef TFH
}

// Device threefry with IMAD-balanced adds. Returns x0 ^ x1 for counter (0, i).
static __device__ __forceinline__ uint32_t tf_bits32(
    uint32_t k0, uint32_t k1, uint32_t ks2, uint32_t idx, uint32_t one) {
    uint32_t x0 = k0;              // 0 + k0
    uint32_t x1 = idx + k1;
#define TF_R(r) { x0 = madd(x1, one, x0); x1 = rotl32(x1, r); x1 ^= x0; }
    TF_R(13) TF_R(15) TF_R(26) TF_R(6)
    x0 = madd(k1, one, x0);  x1 += ks2 + 1u;
    TF_R(17) TF_R(29) TF_R(16) TF_R(24)
    x0 = madd(ks2, one, x0); x1 += k0 + 2u;
    TF_R(13) TF_R(15) TF_R(26) TF_R(6)
    x0 = madd(k0, one, x0);  x1 += k1 + 3u;
    TF_R(17) TF_R(29) TF_R(16) TF_R(24)
    x0 = madd(k1, one, x0);  x1 += ks2 + 4u;
    TF_R(13) TF_R(15) TF_R(26) TF_R(6)
    x0 = madd(ks2, one, x0); x1 += k0 + 5u;
#undef TF_R
    return x0 ^ x1;
}

static __device__ __forceinline__ float bits_to_u01(uint32_t bits) {
    return __uint_as_float((bits >> 9) | 0x3F800000u) - 1.0f;
}

// XLA f32 erfinv (Giles polynomial)
static __device__ __forceinline__ float erfinv_f32(float x) {
    float w = -log1pf(-x * x);
    float p;
    if (w < 5.0f) {
        w -= 2.5f;
        p = 2.81022636e-08f;
        p = fmaf(p, w, 3.43273939e-07f);
        p = fmaf(p, w, -3.5233877e-06f);
        p = fmaf(p, w, -4.39150654e-06f);
        p = fmaf(p, w, 0.00021858087f);
        p = fmaf(p, w, -0.00125372503f);
        p = fmaf(p, w, -0.00417768164f);
        p = fmaf(p, w, 0.246640727f);
        p = fmaf(p, w, 1.50140941f);
    } else {
        w = sqrtf(w) - 3.0f;
        p = -0.000200214257f;
        p = fmaf(p, w, 0.000100950558f);
        p = fmaf(p, w, 0.00134934322f);
        p = fmaf(p, w, -0.00367342844f);
        p = fmaf(p, w, 0.00573950773f);
        p = fmaf(p, w, -0.0076224613f);
        p = fmaf(p, w, 0.00943887047f);
        p = fmaf(p, w, 1.00167406f);
        p = fmaf(p, w, 2.83297682f);
    }
    return p * x;
}

// ---------------------------------------------------------------------------
// Disc: one warp handles TWO 64-wide groups (4 elems/thread, 4 threefry chains)
// ---------------------------------------------------------------------------
__global__ void __launch_bounds__(256)
disc_kernel(const float* __restrict__ latent, float* __restrict__ out,
            uint32_t kg0, uint32_t kg1, int n_pairs, uint32_t one) {
    int wg = (blockIdx.x * blockDim.x + threadIdx.x) >> 5;   // warp -> group pair
    if (wg >= n_pairs) return;
    int lane = threadIdx.x & 31;
    uint32_t ks2 = kg0 ^ kg1 ^ 0x1BD11BDAu;

    int b  = wg >> 4;                 // / 16 pairs per row
    int gp = wg & 15;                 // pair index within row

    const float* row = latent + (size_t)b * ROW_LEN + (size_t)gp * 128;
    float a0 = row[lane];
    float a1 = row[lane + 32];
    float c0 = row[lane + 64];
    float c1 = row[lane + 96];

    // threefry noise (4 independent chains, start early for ILP)
    uint32_t base = ((uint32_t)wg << 7) + (uint32_t)lane;
    uint32_t bitsA0 = tf_bits32(kg0, kg1, ks2, base,       one);
    uint32_t bitsA1 = tf_bits32(kg0, kg1, ks2, base + 32u, one);
    uint32_t bitsC0 = tf_bits32(kg0, kg1, ks2, base + 64u, one);
    uint32_t bitsC1 = tf_bits32(kg0, kg1, ks2, base + 96u, one);

    // softmax #1, groups A and C interleaved
    float mA = fmaxf(a0, a1);
    float mC = fmaxf(c0, c1);
#pragma unroll
    for (int o = 16; o; o >>= 1) {
        mA = fmaxf(mA, __shfl_xor_sync(0xffffffffu, mA, o));
        mC = fmaxf(mC, __shfl_xor_sync(0xffffffffu, mC, o));
    }
    float eA0 = __expf(a0 - mA), eA1 = __expf(a1 - mA);
    float eC0 = __expf(c0 - mC), eC1 = __expf(c1 - mC);
    float sA = eA0 + eA1, sC = eC0 + eC1;
#pragma unroll
    for (int o = 16; o; o >>= 1) {
        sA += __shfl_xor_sync(0xffffffffu, sA, o);
        sC += __shfl_xor_sync(0xffffffffu, sC, o);
    }
    float rA = 1.0f / sA, rC = 1.0f / sC;
    float pA0 = eA0 * rA, pA1 = eA1 * rA;
    float pC0 = eC0 * rC, pC1 = eC1 * rC;

    const float TINY = 1.17549435e-38f;
    float gA0 = -__logf(-__logf(fmaxf(TINY, bits_to_u01(bitsA0))));
    float gA1 = -__logf(-__logf(fmaxf(TINY, bits_to_u01(bitsA1))));
    float gC0 = -__logf(-__logf(fmaxf(TINY, bits_to_u01(bitsC0))));
    float gC1 = -__logf(-__logf(fmaxf(TINY, bits_to_u01(bitsC1))));

    // softmax #2 over (p + g)/tau, tau = 0.5
    float tA0 = (pA0 + gA0) * 2.0f, tA1 = (pA1 + gA1) * 2.0f;
    float tC0 = (pC0 + gC0) * 2.0f, tC1 = (pC1 + gC1) * 2.0f;
    float m2A = fmaxf(tA0, tA1), m2C = fmaxf(tC0, tC1);
#pragma unroll
    for (int o = 16; o; o >>= 1) {
        m2A = fmaxf(m2A, __shfl_xor_sync(0xffffffffu, m2A, o));
        m2C = fmaxf(m2C, __shfl_xor_sync(0xffffffffu, m2C, o));
    }
    float fA0 = __expf(tA0 - m2A), fA1 = __expf(tA1 - m2A);
    float fC0 = __expf(tC0 - m2C), fC1 = __expf(tC1 - m2C);
    float s2A = fA0 + fA1, s2C = fC0 + fC1;
#pragma unroll
    for (int o = 16; o; o >>= 1) {
        s2A += __shfl_xor_sync(0xffffffffu, s2A, o);
        s2C += __shfl_xor_sync(0xffffffffu, s2C, o);
    }
    float r2A = 1.0f / s2A, r2C = 1.0f / s2C;

    float* orow = out + (size_t)b * SAMPLE_LEN + (size_t)gp * 128;
    orow[lane]      = fA0 * r2A;
    orow[lane + 32] = fA1 * r2A;
    orow[lane + 64] = fC0 * r2C;
    orow[lane + 96] = fC1 * r2C;
}

// ---------------------------------------------------------------------------
// Cont: 4 elements/thread, vectorized loads/stores
// ---------------------------------------------------------------------------
__global__ void __launch_bounds__(256)
cont_kernel(const float* __restrict__ latent, float* __restrict__ out,
            uint32_t kn0, uint32_t kn1, int n_quads, int B, uint32_t one) {
    int q = blockIdx.x * blockDim.x + threadIdx.x;
    if (q >= n_quads) return;
    uint32_t ks2 = kn0 ^ kn1 ^ 0x1BD11BDAu;

    int i = q * 4;          // first flat element
    int b = i >> 9;         // / CONT_LEN
    int j = i & 511;        // % CONT_LEN (multiple of 4)

    const float4* cptr = (const float4*)(latent + (size_t)b * ROW_LEN + DISC_LEN + (size_t)j * 2);
    float4 v0 = cptr[0];    // (m0, lv0, m1, lv1)
    float4 v1 = cptr[1];    // (m2, lv2, m3, lv3)

    uint32_t bits0 = tf_bits32(kn0, kn1, ks2, (uint32_t)i,      one);
    uint32_t bits1 = tf_bits32(kn0, kn1, ks2, (uint32_t)i + 1u, one);
    uint32_t bits2 = tf_bits32(kn0, kn1, ks2, (uint32_t)i + 2u, one);
    uint32_t bits3 = tf_bits32(kn0, kn1, ks2, (uint32_t)i + 3u, one);

    const float LO = -0.99999994f;      // nextafter(-1, 0)
    float u0 = fmaxf(LO, fmaf(bits_to_u01(bits0), 2.0f, LO));
    float u1 = fmaxf(LO, fmaf(bits_to_u01(bits1), 2.0f, LO));
    float u2 = fmaxf(LO, fmaf(bits_to_u01(bits2), 2.0f, LO));
    float u3 = fmaxf(LO, fmaf(bits_to_u01(bits3), 2.0f, LO));
    float e0 = 1.41421356f * erfinv_f32(u0);
    float e1 = 1.41421356f * erfinv_f32(u1);
    float e2 = 1.41421356f * erfinv_f32(u2);
    float e3 = 1.41421356f * erfinv_f32(u3);

    float4 cs;
    cs.x = fmaf(__expf(0.5f * v0.y), e0, v0.x);
    cs.y = fmaf(__expf(0.5f * v0.w), e1, v0.z);
    cs.z = fmaf(__expf(0.5f * v1.y), e2, v1.x);
    cs.w = fmaf(__expf(0.5f * v1.w), e3, v1.z);

    float4 mn = make_float4(v0.x, v0.z, v1.x, v1.z);
    float4 lv = make_float4(v0.y, v0.w, v1.y, v1.w);

    size_t sample_total = (size_t)B * SAMPLE_LEN;
    *(float4*)(out + (size_t)b * SAMPLE_LEN + DISC_LEN + j) = cs;
    *(float4*)(out + sample_total + (size_t)i) = mn;
    *(float4*)(out + sample_total + (size_t)B * CONT_LEN + (size_t)i) = lv;
}

// ---------------------------------------------------------------------------
// Launch
// ---------------------------------------------------------------------------
extern "C" void kernel_launch(void* const* d_in, const int* in_sizes, int n_in,
                              void* d_out, int out_size) {
    const float* latent = (const float*)d_in[0];
    float* out = (float*)d_out;
    int B = in_sizes[0] / ROW_LEN;

    // Partitionable split of key(42) = (0, 42): subkey[i] = threefry((0,42), (0,i))
    uint32_t kg0 = 0u, kg1 = 0u;
    threefry2x32_host(0u, 42u, kg0, kg1);
    uint32_t kn0 = 0u, kn1 = 1u;
    threefry2x32_host(0u, 42u, kn0, kn1);

    uint32_t one = 1u;   // opaque multiplier (forces IMAD.LO pipe balance)

    int n_pairs = B * (N_CATEG / 2);                  // warps for disc (2 groups/warp)
    int disc_threads = 256;
    int disc_blocks = (n_pairs * 32 + disc_threads - 1) / disc_threads;
    disc_kernel<<<disc_blocks, disc_threads>>>(latent, out, kg0, kg1, n_pairs, one);

    int n_quads = (B * CONT_LEN) / 4;
    int cont_threads = 256;
    int cont_blocks = (n_quads + cont_threads - 1) / cont_threads;
    cont_kernel<<<cont_blocks, cont_threads>>>(latent, out, kn0, kn1, n_quads, B, one);
}

// round 6
// speedup vs baseline: 1.2220x; 1.0939x over previous
#include <cuda_runtime.h>
#include <cstdint>
#include <cstddef>

// ---------------------------------------------------------------------------
// JointSampling: gumbel-softmax (disc) + reparameterized gaussian (cont)
// JAX partitionable threefry2x32:
//   random_bits32(key, i) = x0 ^ x1 of threefry(key, (0, i))
//   split(key)[i]         = both output words of threefry(key, (0, i))
// Input : latent [B, 3072] f32
// Output: [ sample (B*2560) | mean (B*512) | logvar (B*512) ]  f32
// ---------------------------------------------------------------------------

#define N_CATEG 32
#define CATEG_N 64
#define DISC_LEN 2048
#define CONT_LEN 512
#define ROW_LEN 3072
#define SAMPLE_LEN 2560

static __device__ __forceinline__ uint32_t rotl32(uint32_t x, int r) {
    return __funnelshift_l(x, x, r);
}

// opaque-multiplier add: emits IMAD.LO (fma pipe) because `one` is a runtime reg
static __device__ __forceinline__ uint32_t madd(uint32_t a, uint32_t one, uint32_t c) {
    return a * one + c;
}

// Host-side reference threefry (plain adds)
static __host__ void threefry2x32_host(uint32_t k0, uint32_t k1, uint32_t& x0, uint32_t& x1) {
    uint32_t ks2 = k0 ^ k1 ^ 0x1BD11BDAu;
    x0 += k0; x1 += k1;
#define TFH(r) { x0 += x1; x1 = (x1 << r) | (x1 >> (32 - r)); x1 ^= x0; }
    TFH(13) TFH(15) TFH(26) TFH(6)
    x0 += k1;  x1 += ks2 + 1u;
    TFH(17) TFH(29) TFH(16) TFH(24)
    x0 += ks2; x1 += k0 + 2u;
    TFH(13) TFH(15) TFH(26) TFH(6)
    x0 += k0;  x1 += k1 + 3u;
    TFH(17) TFH(29) TFH(16) TFH(24)
    x0 += k1;  x1 += ks2 + 4u;
    TFH(13) TFH(15) TFH(26) TFH(6)
    x0 += ks2; x1 += k0 + 5u;
#undef TFH
}

// Device threefry with IMAD-balanced adds. Returns x0 ^ x1 for counter (0, i).
static __device__ __forceinline__ uint32_t tf_bits32(
    uint32_t k0, uint32_t k1, uint32_t ks2, uint32_t idx, uint32_t one) {
    uint32_t x0 = k0;              // 0 + k0
    uint32_t x1 = idx + k1;
#define TF_R(r) { x0 = madd(x1, one, x0); x1 = rotl32(x1, r); x1 ^= x0; }
    TF_R(13) TF_R(15) TF_R(26) TF_R(6)
    x0 = madd(k1, one, x0);  x1 += ks2 + 1u;
    TF_R(17) TF_R(29) TF_R(16) TF_R(24)
    x0 = madd(ks2, one, x0); x1 += k0 + 2u;
    TF_R(13) TF_R(15) TF_R(26) TF_R(6)
    x0 = madd(k0, one, x0);  x1 += k1 + 3u;
    TF_R(17) TF_R(29) TF_R(16) TF_R(24)
    x0 = madd(k1, one, x0);  x1 += ks2 + 4u;
    TF_R(13) TF_R(15) TF_R(26) TF_R(6)
    x0 = madd(ks2, one, x0); x1 += k0 + 5u;
#undef TF_R
    return x0 ^ x1;
}

static __device__ __forceinline__ float bits_to_u01(uint32_t bits) {
    return __uint_as_float((bits >> 9) | 0x3F800000u) - 1.0f;
}

// butterfly warp sum (shuffle-based; redux.f32 not available on sm_100)
static __device__ __forceinline__ float warp_sum(float v) {
#pragma unroll
    for (int o = 16; o; o >>= 1) v += __shfl_xor_sync(0xffffffffu, v, o);
    return v;
}

// XLA f32 erfinv (Giles polynomial), log1pf replaced by MUFU log
static __device__ __forceinline__ float erfinv_f32(float x) {
    float w = -__logf(fmaf(-x, x, 1.0f));
    float p;
    if (w < 5.0f) {
        w -= 2.5f;
        p = 2.81022636e-08f;
        p = fmaf(p, w, 3.43273939e-07f);
        p = fmaf(p, w, -3.5233877e-06f);
        p = fmaf(p, w, -4.39150654e-06f);
        p = fmaf(p, w, 0.00021858087f);
        p = fmaf(p, w, -0.00125372503f);
        p = fmaf(p, w, -0.00417768164f);
        p = fmaf(p, w, 0.246640727f);
        p = fmaf(p, w, 1.50140941f);
    } else {
        w = sqrtf(w) - 3.0f;
        p = -0.000200214257f;
        p = fmaf(p, w, 0.000100950558f);
        p = fmaf(p, w, 0.00134934322f);
        p = fmaf(p, w, -0.00367342844f);
        p = fmaf(p, w, 0.00573950773f);
        p = fmaf(p, w, -0.0076224613f);
        p = fmaf(p, w, 0.00943887047f);
        p = fmaf(p, w, 1.00167406f);
        p = fmaf(p, w, 2.83297682f);
    }
    return p * x;
}

// ---------------------------------------------------------------------------
// Fused kernel: blocks [0, n_disc_blocks) do disc, the rest do cont.
// Softmaxes computed WITHOUT max-subtraction (safe: inputs bounded, f32 range
// ample; ratio identical to ~1 ulp). Saves 2 butterfly trees per group.
// ---------------------------------------------------------------------------
__global__ void __launch_bounds__(256)
fused_kernel(const float* __restrict__ latent, float* __restrict__ out,
             uint32_t kg0, uint32_t kg1, uint32_t kn0, uint32_t kn1,
             int n_disc_blocks, int n_pairs, int n_quads, int B, uint32_t one) {
    if (blockIdx.x < (unsigned)n_disc_blocks) {
        // ------------------- disc: one warp = two 64-wide groups -------------
        int wg = blockIdx.x * 8 + (threadIdx.x >> 5);
        if (wg >= n_pairs) return;
        int lane = threadIdx.x & 31;
        uint32_t ks2 = kg0 ^ kg1 ^ 0x1BD11BDAu;

        int b  = wg >> 4;                 // / 16 pairs per row
        int gp = wg & 15;                 // pair index within row

        const float* row = latent + (size_t)b * ROW_LEN + (size_t)gp * 128;
        float a0 = row[lane];
        float a1 = row[lane + 32];
        float c0 = row[lane + 64];
        float c1 = row[lane + 96];

        // threefry noise (4 independent chains, start early for ILP)
        uint32_t base = ((uint32_t)wg << 7) + (uint32_t)lane;
        uint32_t bitsA0 = tf_bits32(kg0, kg1, ks2, base,       one);
        uint32_t bitsA1 = tf_bits32(kg0, kg1, ks2, base + 32u, one);
        uint32_t bitsC0 = tf_bits32(kg0, kg1, ks2, base + 64u, one);
        uint32_t bitsC1 = tf_bits32(kg0, kg1, ks2, base + 96u, one);

        // softmax #1 (no max-subtraction)
        float eA0 = __expf(a0), eA1 = __expf(a1);
        float eC0 = __expf(c0), eC1 = __expf(c1);
        float sA = warp_sum(eA0 + eA1);
        float sC = warp_sum(eC0 + eC1);
        float rA = 1.0f / sA, rC = 1.0f / sC;
        float pA0 = eA0 * rA, pA1 = eA1 * rA;
        float pC0 = eC0 * rC, pC1 = eC1 * rC;

        const float TINY = 1.17549435e-38f;
        float gA0 = -__logf(-__logf(fmaxf(TINY, bits_to_u01(bitsA0))));
        float gA1 = -__logf(-__logf(fmaxf(TINY, bits_to_u01(bitsA1))));
        float gC0 = -__logf(-__logf(fmaxf(TINY, bits_to_u01(bitsC0))));
        float gC1 = -__logf(-__logf(fmaxf(TINY, bits_to_u01(bitsC1))));

        // softmax #2 over (p + g)/tau, tau = 0.5 (no max-subtraction)
        float fA0 = __expf((pA0 + gA0) * 2.0f), fA1 = __expf((pA1 + gA1) * 2.0f);
        float fC0 = __expf((pC0 + gC0) * 2.0f), fC1 = __expf((pC1 + gC1) * 2.0f);
        float s2A = warp_sum(fA0 + fA1);
        float s2C = warp_sum(fC0 + fC1);
        float r2A = 1.0f / s2A, r2C = 1.0f / s2C;

        float* orow = out + (size_t)b * SAMPLE_LEN + (size_t)gp * 128;
        orow[lane]      = fA0 * r2A;
        orow[lane + 32] = fA1 * r2A;
        orow[lane + 64] = fC0 * r2C;
        orow[lane + 96] = fC1 * r2C;
    } else {
        // ------------------- cont: 4 elements/thread, vectorized -------------
        int q = (blockIdx.x - n_disc_blocks) * 256 + threadIdx.x;
        if (q >= n_quads) return;
        uint32_t ks2 = kn0 ^ kn1 ^ 0x1BD11BDAu;

        int i = q * 4;          // first flat element
        int b = i >> 9;         // / CONT_LEN
        int j = i & 511;        // % CONT_LEN (multiple of 4)

        const float4* cptr = (const float4*)(latent + (size_t)b * ROW_LEN + DISC_LEN + (size_t)j * 2);
        float4 v0 = cptr[0];    // (m0, lv0, m1, lv1)
        float4 v1 = cptr[1];    // (m2, lv2, m3, lv3)

        uint32_t bits0 = tf_bits32(kn0, kn1, ks2, (uint32_t)i,      one);
        uint32_t bits1 = tf_bits32(kn0, kn1, ks2, (uint32_t)i + 1u, one);
        uint32_t bits2 = tf_bits32(kn0, kn1, ks2, (uint32_t)i + 2u, one);
        uint32_t bits3 = tf_bits32(kn0, kn1, ks2, (uint32_t)i + 3u, one);

        const float LO = -0.99999994f;      // nextafter(-1, 0)
        float u0 = fmaxf(LO, fmaf(bits_to_u01(bits0), 2.0f, LO));
        float u1 = fmaxf(LO, fmaf(bits_to_u01(bits1), 2.0f, LO));
        float u2 = fmaxf(LO, fmaf(bits_to_u01(bits2), 2.0f, LO));
        float u3 = fmaxf(LO, fmaf(bits_to_u01(bits3), 2.0f, LO));
        float e0 = 1.41421356f * erfinv_f32(u0);
        float e1 = 1.41421356f * erfinv_f32(u1);
        float e2 = 1.41421356f * erfinv_f32(u2);
        float e3 = 1.41421356f * erfinv_f32(u3);

        float4 cs;
        cs.x = fmaf(__expf(0.5f * v0.y), e0, v0.x);
        cs.y = fmaf(__expf(0.5f * v0.w), e1, v0.z);
        cs.z = fmaf(__expf(0.5f * v1.y), e2, v1.x);
        cs.w = fmaf(__expf(0.5f * v1.w), e3, v1.z);

        float4 mn = make_float4(v0.x, v0.z, v1.x, v1.z);
        float4 lv = make_float4(v0.y, v0.w, v1.y, v1.w);

        size_t sample_total = (size_t)B * SAMPLE_LEN;
        *(float4*)(out + (size_t)b * SAMPLE_LEN + DISC_LEN + j) = cs;
        *(float4*)(out + sample_total + (size_t)i) = mn;
        *(float4*)(out + sample_total + (size_t)B * CONT_LEN + (size_t)i) = lv;
    }
}

// ---------------------------------------------------------------------------
// Launch
// ---------------------------------------------------------------------------
extern "C" void kernel_launch(void* const* d_in, const int* in_sizes, int n_in,
                              void* d_out, int out_size) {
    const float* latent = (const float*)d_in[0];
    float* out = (float*)d_out;
    int B = in_sizes[0] / ROW_LEN;

    // Partitionable split of key(42) = (0, 42): subkey[i] = threefry((0,42), (0,i))
    uint32_t kg0 = 0u, kg1 = 0u;
    threefry2x32_host(0u, 42u, kg0, kg1);
    uint32_t kn0 = 0u, kn1 = 1u;
    threefry2x32_host(0u, 42u, kn0, kn1);

    uint32_t one = 1u;   // opaque multiplier (forces IMAD.LO pipe balance)

    int n_pairs = B * (N_CATEG / 2);                     // 2 groups per warp
    int n_disc_blocks = (n_pairs + 7) / 8;               // 8 warps per block
    int n_quads = (B * CONT_LEN) / 4;
    int n_cont_blocks = (n_quads + 255) / 256;

    fused_kernel<<<n_disc_blocks + n_cont_blocks, 256>>>(
        latent, out, kg0, kg1, kn0, kn1,
        n_disc_blocks, n_pairs, n_quads, B, one);
}

// round 7
// speedup vs baseline: 1.3120x; 1.0736x over previous
#include <cuda_runtime.h>
#include <cstdint>
#include <cstddef>

// ---------------------------------------------------------------------------
// JointSampling: gumbel-softmax (disc) + reparameterized gaussian (cont)
// JAX partitionable threefry2x32:
//   random_bits32(key, i) = x0 ^ x1 of threefry(key, (0, i))
//   split(key)[i]         = both output words of threefry(key, (0, i))
// Input : latent [B, 3072] f32
// Output: [ sample (B*2560) | mean (B*512) | logvar (B*512) ]  f32
// ---------------------------------------------------------------------------

#define N_CATEG 32
#define CATEG_N 64
#define DISC_LEN 2048
#define CONT_LEN 512
#define ROW_LEN 3072
#define SAMPLE_LEN 2560

static __device__ __forceinline__ uint32_t rotl32(uint32_t x, int r) {
    return __funnelshift_l(x, x, r);
}

// opaque-multiplier add: emits IMAD.LO (fma pipe) because `one` is a runtime reg
static __device__ __forceinline__ uint32_t madd(uint32_t a, uint32_t one, uint32_t c) {
    return a * one + c;
}

// fast approximate reciprocal (1 MUFU; rel err ~2^-22, fine vs 1e-3 tol)
static __device__ __forceinline__ float frcp(float x) {
    float r;
    asm("rcp.approx.ftz.f32 %0, %1;" : "=f"(r) : "f"(x));
    return r;
}

// Host-side reference threefry (plain adds)
static __host__ void threefry2x32_host(uint32_t k0, uint32_t k1, uint32_t& x0, uint32_t& x1) {
    uint32_t ks2 = k0 ^ k1 ^ 0x1BD11BDAu;
    x0 += k0; x1 += k1;
#define TFH(r) { x0 += x1; x1 = (x1 << r) | (x1 >> (32 - r)); x1 ^= x0; }
    TFH(13) TFH(15) TFH(26) TFH(6)
    x0 += k1;  x1 += ks2 + 1u;
    TFH(17) TFH(29) TFH(16) TFH(24)
    x0 += ks2; x1 += k0 + 2u;
    TFH(13) TFH(15) TFH(26) TFH(6)
    x0 += k0;  x1 += k1 + 3u;
    TFH(17) TFH(29) TFH(16) TFH(24)
    x0 += k1;  x1 += ks2 + 4u;
    TFH(13) TFH(15) TFH(26) TFH(6)
    x0 += ks2; x1 += k0 + 5u;
#undef TFH
}

// Device threefry with IMAD-balanced adds. Returns x0 ^ x1 for counter (0, i).
static __device__ __forceinline__ uint32_t tf_bits32(
    uint32_t k0, uint32_t k1, uint32_t ks2, uint32_t idx, uint32_t one) {
    uint32_t x0 = k0;              // 0 + k0
    uint32_t x1 = idx + k1;
#define TF_R(r) { x0 = madd(x1, one, x0); x1 = rotl32(x1, r); x1 ^= x0; }
    TF_R(13) TF_R(15) TF_R(26) TF_R(6)
    x0 = madd(k1, one, x0);  x1 += ks2 + 1u;
    TF_R(17) TF_R(29) TF_R(16) TF_R(24)
    x0 = madd(ks2, one, x0); x1 += k0 + 2u;
    TF_R(13) TF_R(15) TF_R(26) TF_R(6)
    x0 = madd(k0, one, x0);  x1 += k1 + 3u;
    TF_R(17) TF_R(29) TF_R(16) TF_R(24)
    x0 = madd(k1, one, x0);  x1 += ks2 + 4u;
    TF_R(13) TF_R(15) TF_R(26) TF_R(6)
    x0 = madd(ks2, one, x0); x1 += k0 + 5u;
#undef TF_R
    return x0 ^ x1;
}

static __device__ __forceinline__ float bits_to_u01(uint32_t bits) {
    return __uint_as_float((bits >> 9) | 0x3F800000u) - 1.0f;
}

// 4-step butterfly: reduces within each 16-lane half (both groups at once)
static __device__ __forceinline__ float half_warp_sum(float v) {
#pragma unroll
    for (int o = 8; o; o >>= 1) v += __shfl_xor_sync(0xffffffffu, v, o);
    return v;
}

// XLA f32 erfinv (Giles polynomial), log1pf replaced by MUFU log
static __device__ __forceinline__ float erfinv_f32(float x) {
    float w = -__logf(fmaf(-x, x, 1.0f));
    float p;
    if (w < 5.0f) {
        w -= 2.5f;
        p = 2.81022636e-08f;
        p = fmaf(p, w, 3.43273939e-07f);
        p = fmaf(p, w, -3.5233877e-06f);
        p = fmaf(p, w, -4.39150654e-06f);
        p = fmaf(p, w, 0.00021858087f);
        p = fmaf(p, w, -0.00125372503f);
        p = fmaf(p, w, -0.00417768164f);
        p = fmaf(p, w, 0.246640727f);
        p = fmaf(p, w, 1.50140941f);
    } else {
        w = sqrtf(w) - 3.0f;
        p = -0.000200214257f;
        p = fmaf(p, w, 0.000100950558f);
        p = fmaf(p, w, 0.00134934322f);
        p = fmaf(p, w, -0.00367342844f);
        p = fmaf(p, w, 0.00573950773f);
        p = fmaf(p, w, -0.0076224613f);
        p = fmaf(p, w, 0.00943887047f);
        p = fmaf(p, w, 1.00167406f);
        p = fmaf(p, w, 2.83297682f);
    }
    return p * x;
}

// ---------------------------------------------------------------------------
// Fused kernel: blocks [0, n_disc_blocks) do disc, the rest do cont.
// Disc: one warp = 128 consecutive elements (two 64-wide groups in lane halves).
// Thread t owns elements 4t..4t+3 (one float4). Group A = lanes 0-15, C = 16-31.
// Softmaxes without max-subtraction (inputs bounded; ratio identical to ~1ulp).
// ---------------------------------------------------------------------------
__global__ void __launch_bounds__(256)
fused_kernel(const float* __restrict__ latent, float* __restrict__ out,
             uint32_t kg0, uint32_t kg1, uint32_t kn0, uint32_t kn1,
             int n_disc_blocks, int n_pairs, int n_quads, int B, uint32_t one) {
    if (blockIdx.x < (unsigned)n_disc_blocks) {
        // ------------------- disc -------------------
        int wg = blockIdx.x * 8 + (threadIdx.x >> 5);
        if (wg >= n_pairs) return;
        int lane = threadIdx.x & 31;
        uint32_t ks2 = kg0 ^ kg1 ^ 0x1BD11BDAu;

        int b  = wg >> 4;                 // / 16 chunks per row
        int gp = wg & 15;                 // 128-elem chunk within row

        const float4* rowp = (const float4*)(latent + (size_t)b * ROW_LEN + (size_t)gp * 128);
        float4 v = rowp[lane];

        // threefry noise: 4 consecutive counters per thread
        uint32_t base = ((uint32_t)wg << 7) + ((uint32_t)lane << 2);
        uint32_t b0 = tf_bits32(kg0, kg1, ks2, base,      one);
        uint32_t b1 = tf_bits32(kg0, kg1, ks2, base + 1u, one);
        uint32_t b2 = tf_bits32(kg0, kg1, ks2, base + 2u, one);
        uint32_t b3 = tf_bits32(kg0, kg1, ks2, base + 3u, one);

        // softmax #1 (no max-subtraction); one butterfly covers both lane-half groups
        float e0 = __expf(v.x), e1 = __expf(v.y), e2 = __expf(v.z), e3 = __expf(v.w);
        float s = half_warp_sum((e0 + e1) + (e2 + e3));
        float r = frcp(s);
        float p0 = e0 * r, p1 = e1 * r, p2 = e2 * r, p3 = e3 * r;

        const float TINY = 1.17549435e-38f;
        float g0 = -__logf(-__logf(fmaxf(TINY, bits_to_u01(b0))));
        float g1 = -__logf(-__logf(fmaxf(TINY, bits_to_u01(b1))));
        float g2 = -__logf(-__logf(fmaxf(TINY, bits_to_u01(b2))));
        float g3 = -__logf(-__logf(fmaxf(TINY, bits_to_u01(b3))));

        // softmax #2: exp((p+g)/tau) = exp2((p+g) * 2*log2(e)), tau = 0.5
        const float C2 = 2.8853900817779268f;
        float f0 = exp2f((p0 + g0) * C2);
        float f1 = exp2f((p1 + g1) * C2);
        float f2 = exp2f((p2 + g2) * C2);
        float f3 = exp2f((p3 + g3) * C2);
        float s2 = half_warp_sum((f0 + f1) + (f2 + f3));
        float r2 = frcp(s2);

        float4 o4 = make_float4(f0 * r2, f1 * r2, f2 * r2, f3 * r2);
        float4* orow = (float4*)(out + (size_t)b * SAMPLE_LEN + (size_t)gp * 128);
        orow[lane] = o4;
    } else {
        // ------------------- cont: 4 elements/thread, vectorized -------------
        int q = (blockIdx.x - n_disc_blocks) * 256 + threadIdx.x;
        if (q >= n_quads) return;
        uint32_t ks2 = kn0 ^ kn1 ^ 0x1BD11BDAu;

        int i = q * 4;          // first flat element
        int b = i >> 9;         // / CONT_LEN
        int j = i & 511;        // % CONT_LEN (multiple of 4)

        const float4* cptr = (const float4*)(latent + (size_t)b * ROW_LEN + DISC_LEN + (size_t)j * 2);
        float4 v0 = cptr[0];    // (m0, lv0, m1, lv1)
        float4 v1 = cptr[1];    // (m2, lv2, m3, lv3)

        uint32_t bits0 = tf_bits32(kn0, kn1, ks2, (uint32_t)i,      one);
        uint32_t bits1 = tf_bits32(kn0, kn1, ks2, (uint32_t)i + 1u, one);
        uint32_t bits2 = tf_bits32(kn0, kn1, ks2, (uint32_t)i + 2u, one);
        uint32_t bits3 = tf_bits32(kn0, kn1, ks2, (uint32_t)i + 3u, one);

        const float LO = -0.99999994f;      // nextafter(-1, 0)
        float u0 = fmaxf(LO, fmaf(bits_to_u01(bits0), 2.0f, LO));
        float u1 = fmaxf(LO, fmaf(bits_to_u01(bits1), 2.0f, LO));
        float u2 = fmaxf(LO, fmaf(bits_to_u01(bits2), 2.0f, LO));
        float u3 = fmaxf(LO, fmaf(bits_to_u01(bits3), 2.0f, LO));
        float e0 = 1.41421356f * erfinv_f32(u0);
        float e1 = 1.41421356f * erfinv_f32(u1);
        float e2 = 1.41421356f * erfinv_f32(u2);
        float e3 = 1.41421356f * erfinv_f32(u3);

        float4 cs;
        cs.x = fmaf(__expf(0.5f * v0.y), e0, v0.x);
        cs.y = fmaf(__expf(0.5f * v0.w), e1, v0.z);
        cs.z = fmaf(__expf(0.5f * v1.y), e2, v1.x);
        cs.w = fmaf(__expf(0.5f * v1.w), e3, v1.z);

        float4 mn = make_float4(v0.x, v0.z, v1.x, v1.z);
        float4 lv = make_float4(v0.y, v0.w, v1.y, v1.w);

        size_t sample_total = (size_t)B * SAMPLE_LEN;
        *(float4*)(out + (size_t)b * SAMPLE_LEN + DISC_LEN + j) = cs;
        *(float4*)(out + sample_total + (size_t)i) = mn;
        *(float4*)(out + sample_total + (size_t)B * CONT_LEN + (size_t)i) = lv;
    }
}

// ---------------------------------------------------------------------------
// Launch
// ---------------------------------------------------------------------------
extern "C" void kernel_launch(void* const* d_in, const int* in_sizes, int n_in,
                              void* d_out, int out_size) {
    const float* latent = (const float*)d_in[0];
    float* out = (float*)d_out;
    int B = in_sizes[0] / ROW_LEN;

    // Partitionable split of key(42) = (0, 42): subkey[i] = threefry((0,42), (0,i))
    uint32_t kg0 = 0u, kg1 = 0u;
    threefry2x32_host(0u, 42u, kg0, kg1);
    uint32_t kn0 = 0u, kn1 = 1u;
    threefry2x32_host(0u, 42u, kn0, kn1);

    uint32_t one = 1u;   // opaque multiplier (forces IMAD.LO pipe balance)

    int n_pairs = B * (N_CATEG / 2);                     // 128-elem chunks (2 groups/warp)
    int n_disc_blocks = (n_pairs + 7) / 8;               // 8 warps per block
    int n_quads = (B * CONT_LEN) / 4;
    int n_cont_blocks = (n_quads + 255) / 256;

    fused_kernel<<<n_disc_blocks + n_cont_blocks, 256>>>(
        latent, out, kg0, kg1, kn0, kn1,
        n_disc_blocks, n_pairs, n_quads, B, one);
}

// round 8
// speedup vs baseline: 1.4068x; 1.0723x over previous
#include <cuda_runtime.h>
#include <cstdint>
#include <cstddef>

// ---------------------------------------------------------------------------
// JointSampling: gumbel-softmax (disc) + reparameterized gaussian (cont)
// JAX partitionable threefry2x32:
//   random_bits32(key, i) = x0 ^ x1 of threefry(key, (0, i))
//   split(key)[i]         = both output words of threefry(key, (0, i))
// Input : latent [B, 3072] f32
// Output: [ sample (B*2560) | mean (B*512) | logvar (B*512) ]  f32
// ---------------------------------------------------------------------------

#define N_CATEG 32
#define CATEG_N 64
#define DISC_LEN 2048
#define CONT_LEN 512
#define ROW_LEN 3072
#define SAMPLE_LEN 2560

static __device__ __forceinline__ uint32_t rotl32(uint32_t x, int r) {
    return __funnelshift_l(x, x, r);
}

// opaque-multiplier add: emits IMAD.LO (fma pipe) because `one` is a runtime reg
static __device__ __forceinline__ uint32_t madd(uint32_t a, uint32_t one, uint32_t c) {
    return a * one + c;
}

static __device__ __forceinline__ float frcp(float x) {
    float r;
    asm("rcp.approx.ftz.f32 %0, %1;" : "=f"(r) : "f"(x));
    return r;
}
static __device__ __forceinline__ float fex2(float x) {   // raw MUFU.EX2
    float r;
    asm("ex2.approx.ftz.f32 %0, %1;" : "=f"(r) : "f"(x));
    return r;
}
static __device__ __forceinline__ float flg2(float x) {   // raw MUFU.LG2
    float r;
    asm("lg2.approx.ftz.f32 %0, %1;" : "=f"(r) : "f"(x));
    return r;
}

// Host-side reference threefry (plain adds)
static __host__ void threefry2x32_host(uint32_t k0, uint32_t k1, uint32_t& x0, uint32_t& x1) {
    uint32_t ks2 = k0 ^ k1 ^ 0x1BD11BDAu;
    x0 += k0; x1 += k1;
#define TFH(r) { x0 += x1; x1 = (x1 << r) | (x1 >> (32 - r)); x1 ^= x0; }
    TFH(13) TFH(15) TFH(26) TFH(6)
    x0 += k1;  x1 += ks2 + 1u;
    TFH(17) TFH(29) TFH(16) TFH(24)
    x0 += ks2; x1 += k0 + 2u;
    TFH(13) TFH(15) TFH(26) TFH(6)
    x0 += k0;  x1 += k1 + 3u;
    TFH(17) TFH(29) TFH(16) TFH(24)
    x0 += k1;  x1 += ks2 + 4u;
    TFH(13) TFH(15) TFH(26) TFH(6)
    x0 += ks2; x1 += k0 + 5u;
#undef TFH
}

// Device threefry, all adds IMAD-balanced onto the fma pipe.
// Returns x0 ^ x1 for counter (0, i).
static __device__ __forceinline__ uint32_t tf_bits32(
    uint32_t k0, uint32_t k1, uint32_t ks2, uint32_t idx, uint32_t one) {
    uint32_t x0 = k0;
    uint32_t x1 = madd(idx, one, k1);
#define TF_R(r) { x0 = madd(x1, one, x0); x1 = rotl32(x1, r); x1 ^= x0; }
    TF_R(13) TF_R(15) TF_R(26) TF_R(6)
    x0 = madd(k1, one, x0);  x1 = madd(x1, one, ks2 + 1u);
    TF_R(17) TF_R(29) TF_R(16) TF_R(24)
    x0 = madd(ks2, one, x0); x1 = madd(x1, one, k0 + 2u);
    TF_R(13) TF_R(15) TF_R(26) TF_R(6)
    x0 = madd(k0, one, x0);  x1 = madd(x1, one, k1 + 3u);
    TF_R(17) TF_R(29) TF_R(16) TF_R(24)
    x0 = madd(k1, one, x0);  x1 = madd(x1, one, ks2 + 4u);
    TF_R(13) TF_R(15) TF_R(26) TF_R(6)
    x0 = madd(ks2, one, x0); x1 = madd(x1, one, k0 + 5u);
#undef TF_R
    return x0 ^ x1;
}

// bits -> [0,1): bitcast((bits>>9)|0x3f800000) - 1, built on the fma pipe:
//   bits>>9 = umulhi(bits, 1<<23); OR == ADD (disjoint bits) via IMAD.
static __device__ __forceinline__ float bits_to_u01(uint32_t bits, uint32_t one) {
    uint32_t m = __umulhi(bits, 1u << 23);
    return __uint_as_float(madd(m, one, 0x3F800000u)) - 1.0f;
}

// 4-step butterfly: reduces within each 16-lane half (both groups at once)
static __device__ __forceinline__ float half_warp_sum(float v) {
#pragma unroll
    for (int o = 8; o; o >>= 1) v += __shfl_xor_sync(0xffffffffu, v, o);
    return v;
}

// sqrt(2)*erfinv(x), Giles polynomial with sqrt2 pre-folded into coefficients
static __device__ __forceinline__ float sqrt2_erfinv_f32(float x) {
    float w = -__logf(fmaf(-x, x, 1.0f));
    float p;
    if (w < 5.0f) {
        w -= 2.5f;
        p = 3.97465172e-08f;                 // 2.81022636e-08 * sqrt2
        p = fmaf(p, w, 4.85462093e-07f);
        p = fmaf(p, w, -4.98284884e-06f);
        p = fmaf(p, w, -6.21049041e-06f);
        p = fmaf(p, w, 3.09122935e-04f);
        p = fmaf(p, w, -1.77304094e-03f);
        p = fmaf(p, w, -5.90812175e-03f);
        p = fmaf(p, w, 3.48804458e-01f);
        p = fmaf(p, w, 2.12333113e+00f);
    } else {
        w = sqrtf(w) - 3.0f;
        p = -2.83145602e-04f;
        p = fmaf(p, w, 1.42765262e-04f);
        p = fmaf(p, w, 1.90826014e-03f);
        p = fmaf(p, w, -5.19503527e-03f);
        p = fmaf(p, w, 8.11697617e-03f);
        p = fmaf(p, w, -1.07800623e-02f);
        p = fmaf(p, w, 1.33486912e-02f);
        p = fmaf(p, w, 1.41658282e+00f);
        p = fmaf(p, w, 4.00648894e+00f);
    }
    return p * x;
}

// ---------------------------------------------------------------------------
// Fused kernel: blocks [0, n_disc_blocks) do disc, the rest do cont.
// Disc: one warp = 128 consecutive elements (two 64-wide groups in lane halves).
// Softmaxes without max-subtraction (inputs bounded; ratio identical to ~1ulp).
// ---------------------------------------------------------------------------
__global__ void __launch_bounds__(256)
fused_kernel(const float* __restrict__ latent, float* __restrict__ out,
             uint32_t kg0, uint32_t kg1, uint32_t kn0, uint32_t kn1,
             int n_disc_blocks, int n_pairs, int n_quads, int B, uint32_t one) {
    const float LOG2E  = 1.4426950408889634f;     // log2(e)
    const float NLN2   = -0.6931471805599453f;    // -ln(2)
    const float C2     = 2.8853900817779268f;     // 2*log2(e)  (tau = 0.5)
    const float NLN2C2 = NLN2 * C2;               // fold gumbel's -ln2 with C2

    if (blockIdx.x < (unsigned)n_disc_blocks) {
        // ------------------- disc -------------------
        int wg = blockIdx.x * 8 + (threadIdx.x >> 5);
        if (wg >= n_pairs) return;
        int lane = threadIdx.x & 31;
        uint32_t ks2 = kg0 ^ kg1 ^ 0x1BD11BDAu;

        int b  = wg >> 4;                 // / 16 chunks per row
        int gp = wg & 15;                 // 128-elem chunk within row

        const float4* rowp = (const float4*)(latent + (size_t)b * ROW_LEN + (size_t)gp * 128);
        float4 v = rowp[lane];

        // threefry noise: 4 consecutive counters per thread
        uint32_t base = ((uint32_t)wg << 7) + ((uint32_t)lane << 2);
        uint32_t b0 = tf_bits32(kg0, kg1, ks2, base,      one);
        uint32_t b1 = tf_bits32(kg0, kg1, ks2, base + 1u, one);
        uint32_t b2 = tf_bits32(kg0, kg1, ks2, base + 2u, one);
        uint32_t b3 = tf_bits32(kg0, kg1, ks2, base + 3u, one);

        // softmax #1 (no max-subtraction); one butterfly covers both lane-half groups
        float e0 = fex2(v.x * LOG2E), e1 = fex2(v.y * LOG2E);
        float e2 = fex2(v.z * LOG2E), e3 = fex2(v.w * LOG2E);
        float s = half_warp_sum((e0 + e1) + (e2 + e3));
        float rC2 = frcp(s) * C2;         // fold 1/s with tau scaling (per thread)

        // gumbel, folded: gC2 = lg2( -ln2 * lg2(u) ) * (-ln2*C2)
        const float TINY = 1.17549435e-38f;
        float gc0 = flg2(flg2(fmaxf(TINY, bits_to_u01(b0, one))) * NLN2) * NLN2C2;
        float gc1 = flg2(flg2(fmaxf(TINY, bits_to_u01(b1, one))) * NLN2) * NLN2C2;
        float gc2 = flg2(flg2(fmaxf(TINY, bits_to_u01(b2, one))) * NLN2) * NLN2C2;
        float gc3 = flg2(flg2(fmaxf(TINY, bits_to_u01(b3, one))) * NLN2) * NLN2C2;

        // softmax #2: f = ex2( e*(r*C2) + g*C2 )
        float f0 = fex2(fmaf(e0, rC2, gc0));
        float f1 = fex2(fmaf(e1, rC2, gc1));
        float f2 = fex2(fmaf(e2, rC2, gc2));
        float f3 = fex2(fmaf(e3, rC2, gc3));
        float s2 = half_warp_sum((f0 + f1) + (f2 + f3));
        float r2 = frcp(s2);

        float4 o4 = make_float4(f0 * r2, f1 * r2, f2 * r2, f3 * r2);
        float4* orow = (float4*)(out + (size_t)b * SAMPLE_LEN + (size_t)gp * 128);
        orow[lane] = o4;
    } else {
        // ------------------- cont: 4 elements/thread, vectorized -------------
        int q = (blockIdx.x - n_disc_blocks) * 256 + threadIdx.x;
        if (q >= n_quads) return;
        uint32_t ks2 = kn0 ^ kn1 ^ 0x1BD11BDAu;

        int i = q * 4;          // first flat element
        int b = i >> 9;         // / CONT_LEN
        int j = i & 511;        // % CONT_LEN (multiple of 4)

        const float4* cptr = (const float4*)(latent + (size_t)b * ROW_LEN + DISC_LEN + (size_t)j * 2);
        float4 v0 = cptr[0];    // (m0, lv0, m1, lv1)
        float4 v1 = cptr[1];    // (m2, lv2, m3, lv3)

        uint32_t bits0 = tf_bits32(kn0, kn1, ks2, (uint32_t)i,      one);
        uint32_t bits1 = tf_bits32(kn0, kn1, ks2, (uint32_t)i + 1u, one);
        uint32_t bits2 = tf_bits32(kn0, kn1, ks2, (uint32_t)i + 2u, one);
        uint32_t bits3 = tf_bits32(kn0, kn1, ks2, (uint32_t)i + 3u, one);

        const float LO = -0.99999994f;      // nextafter(-1, 0)
        float u0 = fmaxf(LO, fmaf(bits_to_u01(bits0, one), 2.0f, LO));
        float u1 = fmaxf(LO, fmaf(bits_to_u01(bits1, one), 2.0f, LO));
        float u2 = fmaxf(LO, fmaf(bits_to_u01(bits2, one), 2.0f, LO));
        float u3 = fmaxf(LO, fmaf(bits_to_u01(bits3, one), 2.0f, LO));
        float e0 = sqrt2_erfinv_f32(u0);
        float e1 = sqrt2_erfinv_f32(u1);
        float e2 = sqrt2_erfinv_f32(u2);
        float e3 = sqrt2_erfinv_f32(u3);

        const float HLOG2E = 0.7213475204444817f;   // 0.5*log2(e)
        float4 cs;
        cs.x = fmaf(fex2(v0.y * HLOG2E), e0, v0.x);
        cs.y = fmaf(fex2(v0.w * HLOG2E), e1, v0.z);
        cs.z = fmaf(fex2(v1.y * HLOG2E), e2, v1.x);
        cs.w = fmaf(fex2(v1.w * HLOG2E), e3, v1.z);

        float4 mn = make_float4(v0.x, v0.z, v1.x, v1.z);
        float4 lv = make_float4(v0.y, v0.w, v1.y, v1.w);

        size_t sample_total = (size_t)B * SAMPLE_LEN;
        *(float4*)(out + (size_t)b * SAMPLE_LEN + DISC_LEN + j) = cs;
        *(float4*)(out + sample_total + (size_t)i) = mn;
        *(float4*)(out + sample_total + (size_t)B * CONT_LEN + (size_t)i) = lv;
    }
}

// ---------------------------------------------------------------------------
// Launch
// ---------------------------------------------------------------------------
extern "C" void kernel_launch(void* const* d_in, const int* in_sizes, int n_in,
                              void* d_out, int out_size) {
    const float* latent = (const float*)d_in[0];
    float* out = (float*)d_out;
    int B = in_sizes[0] / ROW_LEN;

    // Partitionable split of key(42) = (0, 42): subkey[i] = threefry((0,42), (0,i))
    uint32_t kg0 = 0u, kg1 = 0u;
    threefry2x32_host(0u, 42u, kg0, kg1);
    uint32_t kn0 = 0u, kn1 = 1u;
    threefry2x32_host(0u, 42u, kn0, kn1);

    uint32_t one = 1u;   // opaque multiplier (forces IMAD pipe balance)

    int n_pairs = B * (N_CATEG / 2);                     // 128-elem chunks (2 groups/warp)
    int n_disc_blocks = (n_pairs + 7) / 8;               // 8 warps per block
    int n_quads = (B * CONT_LEN) / 4;
    int n_cont_blocks = (n_quads + 255) / 256;

    fused_kernel<<<n_disc_blocks + n_cont_blocks, 256>>>(
        latent, out, kg0, kg1, kn0, kn1,
        n_disc_blocks, n_pairs, n_quads, B, one);
}